// round 5
// baseline (speedup 1.0000x reference)
#include <cuda_runtime.h>
#include <cuda_fp16.h>
#include <cstdint>

#define N_NODES_MAX   10000
#define NUM_FEAT      384
#define F_HEAD        128
#define NHEADS        3
#define SPH_DIM       15
#define INV_SQRT_FH   0.08838834764831845f   // 1/sqrt(128)

// Edge-stream pipeline config
#define EDGES_TILE    16
#define STAGES        3
#define W_TILE_B      (EDGES_TILE * NUM_FEAT * 4)    // 24576 B
#define SPH_TILE_B    (EDGES_TILE * SPH_DIM * 4)     // 960 B
#define TX_BYTES      (W_TILE_B + SPH_TILE_B)        // 25536 B
#define SMEM_W_OFF    0
#define SMEM_SPH_OFF  (STAGES * W_TILE_B)                      // 73728
#define SMEM_MBAR_OFF (SMEM_SPH_OFF + STAGES * SPH_TILE_B)     // 76608
#define SMEM_EDGE_TOTAL (SMEM_MBAR_OFF + 2 * STAGES * 8)       // 76656

// Scratch: projected q/k in fp16 (device globals: no allocation allowed)
__device__ __half g_qh[N_NODES_MAX * NUM_FEAT];
__device__ __half g_kh[N_NODES_MAX * NUM_FEAT];

struct __align__(8) Half4 { __half2 a, b; };

// ---------------------------------------------------------------------------
// helpers
// ---------------------------------------------------------------------------
__device__ __forceinline__ uint32_t smem_u32(const void* p) {
    return static_cast<uint32_t>(__cvta_generic_to_shared(p));
}
__device__ __forceinline__ void mbar_init(uint32_t a, uint32_t cnt) {
    asm volatile("mbarrier.init.shared.b64 [%0], %1;" :: "r"(a), "r"(cnt) : "memory");
}
__device__ __forceinline__ void mbar_expect_tx(uint32_t a, uint32_t bytes) {
    asm volatile("mbarrier.arrive.expect_tx.shared.b64 _, [%0], %1;"
                 :: "r"(a), "r"(bytes) : "memory");
}
__device__ __forceinline__ void mbar_arrive(uint32_t a) {
    asm volatile("mbarrier.arrive.shared.b64 _, [%0];" :: "r"(a) : "memory");
}
__device__ __forceinline__ void mbar_wait(uint32_t a, uint32_t parity) {
    asm volatile(
        "{\n\t.reg .pred P;\n"
        "WAITLOOP_%=:\n\t"
        "mbarrier.try_wait.parity.acquire.cta.shared::cta.b64 P, [%0], %1, 0x989680;\n\t"
        "@P bra.uni WAITDONE_%=;\n\t"
        "bra.uni WAITLOOP_%=;\n"
        "WAITDONE_%=:\n\t}"
        :: "r"(a), "r"(parity) : "memory");
}
__device__ __forceinline__ void bulk_cp(uint32_t dst, const void* src,
                                        uint32_t bytes, uint32_t mbar) {
    asm volatile(
        "cp.async.bulk.shared::cta.global.mbarrier::complete_tx::bytes "
        "[%0], [%1], %2, [%3];"
        :: "r"(dst), "l"(src), "r"(bytes), "r"(mbar) : "memory");
}

// ---------------------------------------------------------------------------
// mma helpers
// ---------------------------------------------------------------------------
__device__ __forceinline__ void ldsm_x4(uint32_t addr, uint32_t& r0, uint32_t& r1,
                                        uint32_t& r2, uint32_t& r3) {
    asm volatile("ldmatrix.sync.aligned.m8n8.x4.shared.b16 {%0,%1,%2,%3}, [%4];"
                 : "=r"(r0), "=r"(r1), "=r"(r2), "=r"(r3) : "r"(addr));
}
__device__ __forceinline__ void mma16816(float* c, const uint32_t* a,
                                         const uint32_t* b) {
    asm volatile(
        "mma.sync.aligned.m16n8k16.row.col.f32.f16.f16.f32 "
        "{%0,%1,%2,%3}, {%4,%5,%6,%7}, {%8,%9}, {%0,%1,%2,%3};"
        : "+f"(c[0]), "+f"(c[1]), "+f"(c[2]), "+f"(c[3])
        : "r"(a[0]), "r"(a[1]), "r"(a[2]), "r"(a[3]), "r"(b[0]), "r"(b[1]));
}

// ---------------------------------------------------------------------------
// Projection via fp16 tensor cores (unchanged from round 4)
// ---------------------------------------------------------------------------
__global__ __launch_bounds__(256, 2) void proj_kernel(
    const float* __restrict__ x,
    const float* __restrict__ Wq,
    const float* __restrict__ Wk,
    float* __restrict__ out, int out_n,
    int n_nodes)
{
    if (blockIdx.y == 0 && blockIdx.z == 0) {
        for (int i = blockIdx.x * 256 + threadIdx.x; i < out_n; i += gridDim.x * 256)
            out[i] = 0.0f;
    }

    const int h    = blockIdx.y;
    const int row0 = blockIdx.x * 128;
    const bool is_k = (blockIdx.z != 0);
    const float* __restrict__ W = (is_k ? Wk : Wq) + h * F_HEAD * F_HEAD;
    __half* __restrict__ o_base = is_k ? g_kh : g_qh;
    const float scale = is_k ? 1.0f : INV_SQRT_FH;

    __shared__ __half Xs[128][40];
    __shared__ __half Ws[128][40];

    const int tid  = threadIdx.x;
    const int warp = tid >> 5;
    const int lane = tid & 31;
    const int wm   = (warp & 3) * 32;
    const int wn   = (warp >> 2) * 64;

    uint32_t a_addr[2][2];
    #pragma unroll
    for (int mi = 0; mi < 2; mi++)
        #pragma unroll
        for (int ki = 0; ki < 2; ki++)
            a_addr[mi][ki] = smem_u32(
                &Xs[wm + mi * 16 + (lane & 15)][ki * 16 + (lane >> 4) * 8]);

    uint32_t b_addr[4][2];
    {
        const int nrow = (lane & 7) + ((lane >> 4) << 3);
        const int ksel = ((lane >> 3) & 1) * 8;
        #pragma unroll
        for (int nb = 0; nb < 4; nb++)
            #pragma unroll
            for (int ki = 0; ki < 2; ki++)
                b_addr[nb][ki] = smem_u32(&Ws[wn + nb * 16 + nrow][ki * 16 + ksel]);
    }

    float acc[2][8][4];
    #pragma unroll
    for (int mi = 0; mi < 2; mi++)
        #pragma unroll
        for (int ni = 0; ni < 8; ni++)
            #pragma unroll
            for (int c = 0; c < 4; c++) acc[mi][ni][c] = 0.0f;

    for (int k0 = 0; k0 < F_HEAD; k0 += 32) {
        #pragma unroll
        for (int t = tid; t < 128 * 16; t += 256) {
            const int r  = t >> 4;
            const int c2 = t & 15;
            float2 xv = make_float2(0.f, 0.f);
            const int row = row0 + r;
            if (row < n_nodes)
                xv = *(const float2*)&x[(size_t)row * NUM_FEAT + h * F_HEAD + k0 + c2 * 2];
            *(__half2*)&Xs[r][c2 * 2] = __floats2half2_rn(xv.x, xv.y);

            const float2 wv = *(const float2*)&W[(size_t)r * F_HEAD + k0 + c2 * 2];
            *(__half2*)&Ws[r][c2 * 2] = __floats2half2_rn(wv.x, wv.y);
        }
        __syncthreads();

        #pragma unroll
        for (int ki = 0; ki < 2; ki++) {
            uint32_t af[2][4];
            #pragma unroll
            for (int mi = 0; mi < 2; mi++)
                ldsm_x4(a_addr[mi][ki], af[mi][0], af[mi][1], af[mi][2], af[mi][3]);

            uint32_t bf[8][2];
            #pragma unroll
            for (int nb = 0; nb < 4; nb++) {
                uint32_t r0, r1, r2, r3;
                ldsm_x4(b_addr[nb][ki], r0, r1, r2, r3);
                bf[nb * 2 + 0][0] = r0;  bf[nb * 2 + 0][1] = r1;
                bf[nb * 2 + 1][0] = r2;  bf[nb * 2 + 1][1] = r3;
            }

            #pragma unroll
            for (int mi = 0; mi < 2; mi++)
                #pragma unroll
                for (int ni = 0; ni < 8; ni++)
                    mma16816(acc[mi][ni], af[mi], bf[ni]);
        }
        __syncthreads();
    }

    #pragma unroll
    for (int mi = 0; mi < 2; mi++) {
        const int ra = row0 + wm + mi * 16 + (lane >> 2);
        const int rb = ra + 8;
        #pragma unroll
        for (int ni = 0; ni < 8; ni++) {
            const int col = h * F_HEAD + wn + ni * 8 + (lane & 3) * 2;
            if (ra < n_nodes)
                *(__half2*)(o_base + (size_t)ra * NUM_FEAT + col) =
                    __floats2half2_rn(acc[mi][ni][0] * scale, acc[mi][ni][1] * scale);
            if (rb < n_nodes)
                *(__half2*)(o_base + (size_t)rb * NUM_FEAT + col) =
                    __floats2half2_rn(acc[mi][ni][2] * scale, acc[mi][ni][3] * scale);
        }
    }
}

// ---------------------------------------------------------------------------
// Edge kernel: persistent blocks, cp.async.bulk pipelined w_ij/sph stream.
// Ring of STAGES stages x EDGES_TILE edges. tid0 produces (bulk copies under
// mbarrier), 8 warps consume 2 edges each per tile. q/k fp16 gathers via LDG.
// ---------------------------------------------------------------------------
__global__ __launch_bounds__(256) void edge_kernel(
    const float* __restrict__ w_ij,
    const float* __restrict__ sph,
    const int*   __restrict__ idx_i,
    const int*   __restrict__ idx_j,
    const float* __restrict__ phi_r,
    const float* __restrict__ phi_chi,
    float* __restrict__ out,
    int n_pairs)
{
    extern __shared__ __align__(128) char dynsmem[];
    float* wbuf   = (float*)(dynsmem + SMEM_W_OFF);
    float* sphbuf = (float*)(dynsmem + SMEM_SPH_OFF);
    const uint32_t smem_base = smem_u32(dynsmem);
    const uint32_t mb = smem_base + SMEM_MBAR_OFF;
    const uint32_t w_smem   = smem_base + SMEM_W_OFF;
    const uint32_t sph_smem = smem_base + SMEM_SPH_OFF;

    const int tid  = threadIdx.x;
    const int warp = tid >> 5;
    const int lane = tid & 31;

    if (tid == 0) {
        #pragma unroll
        for (int s = 0; s < STAGES; s++) {
            mbar_init(mb + s * 8, 1);                 // full[s]
            mbar_init(mb + STAGES * 8 + s * 8, 8);    // empty[s]
        }
        asm volatile("fence.proxy.async.shared::cta;" ::: "memory");
    }
    __syncthreads();

    const int full_tiles = n_pairs / EDGES_TILE;
    const int G = gridDim.x;

    // Remainder edges (n_pairs % EDGES_TILE): direct-LDG path, block 0 only.
    if (blockIdx.x == 0) {
        for (int e = full_tiles * EDGES_TILE + warp; e < n_pairs; e += 8) {
            const int ni = idx_i[e], nj = idx_j[e];
            const Half4*  q4 = (const Half4*)(g_qh + (size_t)ni * NUM_FEAT);
            const Half4*  k4 = (const Half4*)(g_kh + (size_t)nj * NUM_FEAT);
            const float4* w4 = (const float4*)(w_ij + (size_t)e * NUM_FEAT);
            float a[NHEADS];
            #pragma unroll
            for (int hh = 0; hh < NHEADS; hh++) {
                const int idx = lane + hh * 32;
                const float4 wv = w4[idx];
                const Half4 qh = q4[idx], kh = k4[idx];
                const float2 qa = __half22float2(qh.a), qb = __half22float2(qh.b);
                const float2 ka = __half22float2(kh.a), kb = __half22float2(kh.b);
                a[hh] = qa.x * wv.x * ka.x + qa.y * wv.y * ka.y
                      + qb.x * wv.z * kb.x + qb.y * wv.w * kb.y;
            }
            #pragma unroll
            for (int off = 16; off > 0; off >>= 1)
                #pragma unroll
                for (int hh = 0; hh < NHEADS; hh++)
                    a[hh] += __shfl_xor_sync(0xFFFFFFFFu, a[hh], off);
            const float cut = phi_r[e] + phi_chi[e];
            if (lane < SPH_DIM) {
                const float alpha = (lane < 3 ? a[0] : (lane < 8 ? a[1] : a[2])) * cut;
                atomicAdd(&out[(size_t)ni * SPH_DIM + lane],
                          alpha * sph[(size_t)e * SPH_DIM + lane]);
            }
        }
    }

    // Prologue: issue first STAGES tiles (barriers fresh -> no empty wait).
    if (tid == 0) {
        #pragma unroll
        for (int i = 0; i < STAGES; i++) {
            const int T = blockIdx.x + i * G;
            if (T < full_tiles) {
                mbar_expect_tx(mb + i * 8, TX_BYTES);
                bulk_cp(w_smem + i * W_TILE_B,
                        w_ij + (size_t)T * EDGES_TILE * NUM_FEAT,
                        W_TILE_B, mb + i * 8);
                bulk_cp(sph_smem + i * SPH_TILE_B,
                        sph + (size_t)T * EDGES_TILE * SPH_DIM,
                        SPH_TILE_B, mb + i * 8);
            }
        }
    }

    for (int i = 0; ; i++) {
        const int T = blockIdx.x + i * G;
        if (T >= full_tiles) break;
        const int s = i % STAGES;
        const uint32_t phase = (i / STAGES) & 1u;
        mbar_wait(mb + s * 8, phase);

        // ---- consume: 2 edges per warp from smem tile ----
        const int le0 = warp * 2;
        const int e0  = T * EDGES_TILE + le0;
        const int e1  = e0 + 1;

        const int ni0 = idx_i[e0], nj0 = idx_j[e0];
        const int ni1 = idx_i[e1], nj1 = idx_j[e1];

        const float4* ws0 = (const float4*)(wbuf + (size_t)s * EDGES_TILE * NUM_FEAT
                                                 + (size_t)le0 * NUM_FEAT);
        const float4* ws1 = ws0 + NUM_FEAT / 4;
        const Half4* q0 = (const Half4*)(g_qh + (size_t)ni0 * NUM_FEAT);
        const Half4* k0 = (const Half4*)(g_kh + (size_t)nj0 * NUM_FEAT);
        const Half4* q1 = (const Half4*)(g_qh + (size_t)ni1 * NUM_FEAT);
        const Half4* k1 = (const Half4*)(g_kh + (size_t)nj1 * NUM_FEAT);

        float a0[NHEADS], a1[NHEADS];
        #pragma unroll
        for (int hh = 0; hh < NHEADS; hh++) {
            const int idx = lane + hh * 32;
            const float4 wv0 = ws0[idx];
            const float4 wv1 = ws1[idx];
            const Half4 qh0 = q0[idx], kh0 = k0[idx];
            const Half4 qh1 = q1[idx], kh1 = k1[idx];
            {
                const float2 qa = __half22float2(qh0.a), qb = __half22float2(qh0.b);
                const float2 ka = __half22float2(kh0.a), kb = __half22float2(kh0.b);
                a0[hh] = qa.x * wv0.x * ka.x + qa.y * wv0.y * ka.y
                       + qb.x * wv0.z * kb.x + qb.y * wv0.w * kb.y;
            }
            {
                const float2 qa = __half22float2(qh1.a), qb = __half22float2(qh1.b);
                const float2 ka = __half22float2(kh1.a), kb = __half22float2(kh1.b);
                a1[hh] = qa.x * wv1.x * ka.x + qa.y * wv1.y * ka.y
                       + qb.x * wv1.z * kb.x + qb.y * wv1.w * kb.y;
            }
        }

        // sph rows from smem (before releasing the stage)
        float sv0 = 0.f, sv1 = 0.f;
        if (lane < SPH_DIM) {
            sv0 = sphbuf[(size_t)s * EDGES_TILE * SPH_DIM + le0 * SPH_DIM + lane];
            sv1 = sphbuf[(size_t)s * EDGES_TILE * SPH_DIM + (le0 + 1) * SPH_DIM + lane];
        }

        #pragma unroll
        for (int off = 16; off > 0; off >>= 1) {
            #pragma unroll
            for (int hh = 0; hh < NHEADS; hh++) {
                a0[hh] += __shfl_xor_sync(0xFFFFFFFFu, a0[hh], off);
                a1[hh] += __shfl_xor_sync(0xFFFFFFFFu, a1[hh], off);
            }
        }

        __syncwarp();
        if (lane == 0) mbar_arrive(mb + STAGES * 8 + s * 8);   // empty[s]

        const float cut0 = phi_r[e0] + phi_chi[e0];
        const float cut1 = phi_r[e1] + phi_chi[e1];
        if (lane < SPH_DIM) {
            const float al0 = (lane < 3 ? a0[0] : (lane < 8 ? a0[1] : a0[2])) * cut0;
            atomicAdd(&out[(size_t)ni0 * SPH_DIM + lane], al0 * sv0);
            const float al1 = (lane < 3 ? a1[0] : (lane < 8 ? a1[1] : a1[2])) * cut1;
            atomicAdd(&out[(size_t)ni1 * SPH_DIM + lane], al1 * sv1);
        }

        // ---- produce: refill stage s with tile i+STAGES ----
        if (tid == 0) {
            const int Tn = blockIdx.x + (i + STAGES) * G;
            if (Tn < full_tiles) {
                mbar_wait(mb + STAGES * 8 + s * 8, (i / STAGES) & 1u);  // empty[s]
                mbar_expect_tx(mb + s * 8, TX_BYTES);
                bulk_cp(w_smem + s * W_TILE_B,
                        w_ij + (size_t)Tn * EDGES_TILE * NUM_FEAT,
                        W_TILE_B, mb + s * 8);
                bulk_cp(sph_smem + s * SPH_TILE_B,
                        sph + (size_t)Tn * EDGES_TILE * SPH_DIM,
                        SPH_TILE_B, mb + s * 8);
            }
        }
    }
}

// ---------------------------------------------------------------------------
// Launch. Inputs (metadata order):
//  0: chi (unused)  1: sph_ij  2: x  3: w_ij  4: idx_i  5: phi_r_cut
//  6: phi_chi_cut   7: idx_j   8: Wq 9: Wk
// ---------------------------------------------------------------------------
extern "C" void kernel_launch(void* const* d_in, const int* in_sizes, int n_in,
                              void* d_out, int out_size)
{
    const float* sph     = (const float*)d_in[1];
    const float* x       = (const float*)d_in[2];
    const float* w_ij    = (const float*)d_in[3];
    const int*   idx_i   = (const int*)  d_in[4];
    const float* phi_r   = (const float*)d_in[5];
    const float* phi_chi = (const float*)d_in[6];
    const int*   idx_j   = (const int*)  d_in[7];
    const float* Wq      = (const float*)d_in[8];
    const float* Wk      = (const float*)d_in[9];
    float* out = (float*)d_out;

    const int n_nodes = in_sizes[2] / NUM_FEAT;
    const int n_pairs = in_sizes[4];

    dim3 pgrid((n_nodes + 127) / 128, NHEADS, 2);
    proj_kernel<<<pgrid, 256>>>(x, Wq, Wk, out, out_size, n_nodes);

    static bool attr_set = false;
    if (!attr_set) {
        cudaFuncSetAttribute(edge_kernel,
                             cudaFuncAttributeMaxDynamicSharedMemorySize,
                             SMEM_EDGE_TOTAL);
        attr_set = true;
    }
    const int G = 296;   // 2 blocks/SM persistent
    edge_kernel<<<G, 256, SMEM_EDGE_TOTAL>>>(w_ij, sph, idx_i, idx_j,
                                             phi_r, phi_chi, out, n_pairs);
}

// round 6
// speedup vs baseline: 1.4699x; 1.4699x over previous
#include <cuda_runtime.h>
#include <cuda_fp16.h>
#include <cstdint>

#define N_NODES_MAX   10000
#define ROW_PAD       128
#define NUM_FEAT      384
#define F_HEAD        128
#define NHEADS        3
#define SPH_DIM       15
#define INV_SQRT_FH   0.08838834764831845f   // 1/sqrt(128)

// Scratch (device globals: no allocation allowed)
__device__ __half g_qh[N_NODES_MAX * NUM_FEAT];
__device__ __half g_kh[N_NODES_MAX * NUM_FEAT];
__device__ __half g_xh[(N_NODES_MAX + ROW_PAD) * NUM_FEAT];   // padded fp16 x
__device__ __half g_wqh[NHEADS * F_HEAD * F_HEAD];
__device__ __half g_wkh[NHEADS * F_HEAD * F_HEAD];

struct __align__(8) Half4 { __half2 a, b; };

// ---------------------------------------------------------------------------
// helpers
// ---------------------------------------------------------------------------
__device__ __forceinline__ uint32_t smem_u32(const void* p) {
    return static_cast<uint32_t>(__cvta_generic_to_shared(p));
}
__device__ __forceinline__ void cp16(uint32_t dst, const void* src) {
    asm volatile("cp.async.cg.shared.global [%0], [%1], 16;"
                 :: "r"(dst), "l"(src) : "memory");
}
__device__ __forceinline__ void cp_wait_all() {
    asm volatile("cp.async.commit_group;\n\tcp.async.wait_group 0;" ::: "memory");
}
__device__ __forceinline__ void ldsm_x4(uint32_t addr, uint32_t& r0, uint32_t& r1,
                                        uint32_t& r2, uint32_t& r3) {
    asm volatile("ldmatrix.sync.aligned.m8n8.x4.shared.b16 {%0,%1,%2,%3}, [%4];"
                 : "=r"(r0), "=r"(r1), "=r"(r2), "=r"(r3) : "r"(addr));
}
__device__ __forceinline__ void mma16816(float* c, const uint32_t* a,
                                         const uint32_t* b) {
    asm volatile(
        "mma.sync.aligned.m16n8k16.row.col.f32.f16.f16.f32 "
        "{%0,%1,%2,%3}, {%4,%5,%6,%7}, {%8,%9}, {%0,%1,%2,%3};"
        : "+f"(c[0]), "+f"(c[1]), "+f"(c[2]), "+f"(c[3])
        : "r"(a[0]), "r"(a[1]), "r"(a[2]), "r"(a[3]), "r"(b[0]), "r"(b[1]));
}

// ---------------------------------------------------------------------------
// Pre-convert kernel: x, Wq, Wk -> fp16; zero-init out. Grid-stride.
// ---------------------------------------------------------------------------
__global__ __launch_bounds__(256) void preconv_kernel(
    const float* __restrict__ x,
    const float* __restrict__ Wq,
    const float* __restrict__ Wk,
    float* __restrict__ out, int out_n,
    int n_x)                       // n_nodes * NUM_FEAT (divisible by 8)
{
    const int gid    = blockIdx.x * blockDim.x + threadIdx.x;
    const int stride = gridDim.x * blockDim.x;

    // x -> g_xh, 8 elems per iter
    const int nx8 = n_x >> 3;
    for (int i = gid; i < nx8; i += stride) {
        const float4 a = *(const float4*)&x[i * 8];
        const float4 b = *(const float4*)&x[i * 8 + 4];
        __half2 h[4];
        h[0] = __floats2half2_rn(a.x, a.y);
        h[1] = __floats2half2_rn(a.z, a.w);
        h[2] = __floats2half2_rn(b.x, b.y);
        h[3] = __floats2half2_rn(b.z, b.w);
        *(uint4*)&g_xh[i * 8] = *(const uint4*)h;
    }

    // Wq/Wk -> fp16
    const int nw8 = (NHEADS * F_HEAD * F_HEAD) >> 3;
    for (int i = gid; i < nw8; i += stride) {
        {
            const float4 a = *(const float4*)&Wq[i * 8];
            const float4 b = *(const float4*)&Wq[i * 8 + 4];
            __half2 h[4];
            h[0] = __floats2half2_rn(a.x, a.y);
            h[1] = __floats2half2_rn(a.z, a.w);
            h[2] = __floats2half2_rn(b.x, b.y);
            h[3] = __floats2half2_rn(b.z, b.w);
            *(uint4*)&g_wqh[i * 8] = *(const uint4*)h;
        }
        {
            const float4 a = *(const float4*)&Wk[i * 8];
            const float4 b = *(const float4*)&Wk[i * 8 + 4];
            __half2 h[4];
            h[0] = __floats2half2_rn(a.x, a.y);
            h[1] = __floats2half2_rn(a.z, a.w);
            h[2] = __floats2half2_rn(b.x, b.y);
            h[3] = __floats2half2_rn(b.z, b.w);
            *(uint4*)&g_wkh[i * 8] = *(const uint4*)h;
        }
    }

    // zero out (poisoned to 0xAA)
    for (int i = gid; i < out_n; i += stride) out[i] = 0.0f;
}

// ---------------------------------------------------------------------------
// Projection: fp16 tensor cores, single full-K smem stage via cp.async.
// C-tile 128x128; 8 warps as 4(m) x 2(n), warp tile 32x64; K=128 in one stage.
// Smem pitch 136 halfs (272B) -> ldmatrix conflict-free.
// ---------------------------------------------------------------------------
#define PITCH 136
#define PROJ_SMEM (2 * 128 * PITCH * 2)   // X + W tiles, bytes (69632)

__global__ __launch_bounds__(256, 2) void proj_kernel(int n_nodes)
{
    extern __shared__ __align__(16) __half psmem[];
    __half* Xh = psmem;                  // [128][PITCH]
    __half* Wh = psmem + 128 * PITCH;    // [128][PITCH]

    const int h    = blockIdx.y;
    const int row0 = blockIdx.x * 128;
    const bool is_k = (blockIdx.z != 0);
    const __half* __restrict__ Wsrc = (is_k ? g_wkh : g_wqh) + h * F_HEAD * F_HEAD;
    __half* __restrict__ o_base = is_k ? g_kh : g_qh;
    const float scale = is_k ? 1.0f : INV_SQRT_FH;

    const int tid  = threadIdx.x;
    const int warp = tid >> 5;
    const int lane = tid & 31;
    const int wm   = (warp & 3) * 32;
    const int wn   = (warp >> 2) * 64;

    // ---- stage X and W (full K=128) via cp.async, 16B chunks ----
    // 128 rows x 16 chunks each for X and W
    #pragma unroll
    for (int t = tid; t < 128 * 16; t += 256) {
        const int r = t >> 4, c = t & 15;
        cp16(smem_u32(&Xh[r * PITCH + c * 8]),
             &g_xh[(size_t)(row0 + r) * NUM_FEAT + h * F_HEAD + c * 8]);
        cp16(smem_u32(&Wh[r * PITCH + c * 8]),
             &Wsrc[(size_t)r * F_HEAD + c * 8]);
    }
    cp_wait_all();
    __syncthreads();

    // ---- fragment base addresses (same index pattern as validated R4) ----
    uint32_t a_base[2];
    #pragma unroll
    for (int mi = 0; mi < 2; mi++)
        a_base[mi] = smem_u32(
            &Xh[(wm + mi * 16 + (lane & 15)) * PITCH + (lane >> 4) * 8]);

    uint32_t b_base[4];
    {
        const int nrow = (lane & 7) + ((lane >> 4) << 3);
        const int ksel = ((lane >> 3) & 1) * 8;
        #pragma unroll
        for (int nb = 0; nb < 4; nb++)
            b_base[nb] = smem_u32(&Wh[(wn + nb * 16 + nrow) * PITCH + ksel]);
    }

    float acc[2][8][4];
    #pragma unroll
    for (int mi = 0; mi < 2; mi++)
        #pragma unroll
        for (int ni = 0; ni < 8; ni++)
            #pragma unroll
            for (int c = 0; c < 4; c++) acc[mi][ni][c] = 0.0f;

    #pragma unroll
    for (int ki = 0; ki < 8; ki++) {
        const uint32_t koff = ki * 32;     // 16 halfs = 32B
        uint32_t af[2][4];
        #pragma unroll
        for (int mi = 0; mi < 2; mi++)
            ldsm_x4(a_base[mi] + koff, af[mi][0], af[mi][1], af[mi][2], af[mi][3]);

        uint32_t bf[8][2];
        #pragma unroll
        for (int nb = 0; nb < 4; nb++) {
            uint32_t r0, r1, r2, r3;
            ldsm_x4(b_base[nb] + koff, r0, r1, r2, r3);
            bf[nb * 2 + 0][0] = r0;  bf[nb * 2 + 0][1] = r1;
            bf[nb * 2 + 1][0] = r2;  bf[nb * 2 + 1][1] = r3;
        }

        #pragma unroll
        for (int mi = 0; mi < 2; mi++)
            #pragma unroll
            for (int ni = 0; ni < 8; ni++)
                mma16816(acc[mi][ni], af[mi], bf[ni]);
    }

    // ---- epilogue: scale + fp16 store ----
    #pragma unroll
    for (int mi = 0; mi < 2; mi++) {
        const int ra = row0 + wm + mi * 16 + (lane >> 2);
        const int rb = ra + 8;
        #pragma unroll
        for (int ni = 0; ni < 8; ni++) {
            const int col = h * F_HEAD + wn + ni * 8 + (lane & 3) * 2;
            if (ra < n_nodes)
                *(__half2*)(o_base + (size_t)ra * NUM_FEAT + col) =
                    __floats2half2_rn(acc[mi][ni][0] * scale, acc[mi][ni][1] * scale);
            if (rb < n_nodes)
                *(__half2*)(o_base + (size_t)rb * NUM_FEAT + col) =
                    __floats2half2_rn(acc[mi][ni][2] * scale, acc[mi][ni][3] * scale);
        }
    }
}

// ---------------------------------------------------------------------------
// Edge kernel: one warp per TWO edges (R4 version, verbatim — best measured).
// ---------------------------------------------------------------------------
__global__ __launch_bounds__(256) void edge_kernel(
    const float* __restrict__ w_ij,
    const float* __restrict__ sph,
    const int*   __restrict__ idx_i,
    const int*   __restrict__ idx_j,
    const float* __restrict__ phi_r,
    const float* __restrict__ phi_chi,
    float* __restrict__ out,
    int n_pairs)
{
    const int gw   = (blockIdx.x * blockDim.x + threadIdx.x) >> 5;
    const int lane = threadIdx.x & 31;
    const int e0   = gw * 2;
    if (e0 >= n_pairs) return;
    const bool has2 = (e0 + 1 < n_pairs);
    const int e1 = has2 ? e0 + 1 : e0;

    const int ni0 = idx_i[e0], nj0 = idx_j[e0];
    const int ni1 = idx_i[e1], nj1 = idx_j[e1];

    const Half4*  __restrict__ q0 = (const Half4*)(g_qh + (size_t)ni0 * NUM_FEAT);
    const Half4*  __restrict__ k0 = (const Half4*)(g_kh + (size_t)nj0 * NUM_FEAT);
    const float4* __restrict__ w0 = (const float4*)(w_ij + (size_t)e0 * NUM_FEAT);
    const Half4*  __restrict__ q1 = (const Half4*)(g_qh + (size_t)ni1 * NUM_FEAT);
    const Half4*  __restrict__ k1 = (const Half4*)(g_kh + (size_t)nj1 * NUM_FEAT);
    const float4* __restrict__ w1 = (const float4*)(w_ij + (size_t)e1 * NUM_FEAT);

    float a0[NHEADS], a1[NHEADS];
    #pragma unroll
    for (int hh = 0; hh < NHEADS; hh++) {
        const int idx = lane + hh * 32;
        const float4 wv0 = __ldcs(&w0[idx]);
        const float4 wv1 = __ldcs(&w1[idx]);
        const Half4  qh0 = q0[idx];
        const Half4  kh0 = k0[idx];
        const Half4  qh1 = q1[idx];
        const Half4  kh1 = k1[idx];

        {
            const float2 qa = __half22float2(qh0.a), qb = __half22float2(qh0.b);
            const float2 ka = __half22float2(kh0.a), kb = __half22float2(kh0.b);
            a0[hh] = qa.x * wv0.x * ka.x + qa.y * wv0.y * ka.y
                   + qb.x * wv0.z * kb.x + qb.y * wv0.w * kb.y;
        }
        {
            const float2 qa = __half22float2(qh1.a), qb = __half22float2(qh1.b);
            const float2 ka = __half22float2(kh1.a), kb = __half22float2(kh1.b);
            a1[hh] = qa.x * wv1.x * ka.x + qa.y * wv1.y * ka.y
                   + qb.x * wv1.z * kb.x + qb.y * wv1.w * kb.y;
        }
    }

    #pragma unroll
    for (int off = 16; off > 0; off >>= 1) {
        #pragma unroll
        for (int hh = 0; hh < NHEADS; hh++) {
            a0[hh] += __shfl_xor_sync(0xFFFFFFFFu, a0[hh], off);
            a1[hh] += __shfl_xor_sync(0xFFFFFFFFu, a1[hh], off);
        }
    }

    const float cut0 = phi_r[e0] + phi_chi[e0];
    const float cut1 = phi_r[e1] + phi_chi[e1];

    if (lane < SPH_DIM) {
        const float al0 = (lane < 3 ? a0[0] : (lane < 8 ? a0[1] : a0[2])) * cut0;
        atomicAdd(&out[(size_t)ni0 * SPH_DIM + lane],
                  al0 * __ldcs(&sph[(size_t)e0 * SPH_DIM + lane]));
        if (has2) {
            const float al1 = (lane < 3 ? a1[0] : (lane < 8 ? a1[1] : a1[2])) * cut1;
            atomicAdd(&out[(size_t)ni1 * SPH_DIM + lane],
                      al1 * __ldcs(&sph[(size_t)e1 * SPH_DIM + lane]));
        }
    }
}

// ---------------------------------------------------------------------------
// Launch. Inputs (metadata order):
//  0: chi (unused)  1: sph_ij  2: x  3: w_ij  4: idx_i  5: phi_r_cut
//  6: phi_chi_cut   7: idx_j   8: Wq 9: Wk
// ---------------------------------------------------------------------------
extern "C" void kernel_launch(void* const* d_in, const int* in_sizes, int n_in,
                              void* d_out, int out_size)
{
    const float* sph     = (const float*)d_in[1];
    const float* x       = (const float*)d_in[2];
    const float* w_ij    = (const float*)d_in[3];
    const int*   idx_i   = (const int*)  d_in[4];
    const float* phi_r   = (const float*)d_in[5];
    const float* phi_chi = (const float*)d_in[6];
    const int*   idx_j   = (const int*)  d_in[7];
    const float* Wq      = (const float*)d_in[8];
    const float* Wk      = (const float*)d_in[9];
    float* out = (float*)d_out;

    const int n_nodes = in_sizes[2] / NUM_FEAT;
    const int n_pairs = in_sizes[4];

    static bool attr_set = false;
    if (!attr_set) {
        cudaFuncSetAttribute(proj_kernel,
                             cudaFuncAttributeMaxDynamicSharedMemorySize,
                             PROJ_SMEM);
        attr_set = true;
    }

    // 1) fp16 pre-convert + output zero-init
    preconv_kernel<<<1184, 256>>>(x, Wq, Wk, out, out_size, n_nodes * NUM_FEAT);

    // 2) projections (tensor cores, fp16 in/out)
    dim3 pgrid((n_nodes + 127) / 128, NHEADS, 2);
    proj_kernel<<<pgrid, 256, PROJ_SMEM>>>(n_nodes);

    // 3) edge attention + scatter (R4 best)
    const int edges_per_block = (256 / 32) * 2;
    const int eblocks = (n_pairs + edges_per_block - 1) / edges_per_block;
    edge_kernel<<<eblocks, 256>>>(w_ij, sph, idx_i, idx_j, phi_r, phi_chi,
                                  out, n_pairs);
}

// round 8
// speedup vs baseline: 1.5078x; 1.0257x over previous
#include <cuda_runtime.h>
#include <cuda_fp16.h>
#include <cstdint>

#define N_NODES_MAX   10000
#define NUM_FEAT      384
#define F_HEAD        128
#define NHEADS        3
#define SPH_DIM       15
#define INV_SQRT_FH   0.08838834764831845f   // 1/sqrt(128)

// Scratch: projected q/k in fp16 (device globals: no allocation allowed)
__device__ __half g_qh[N_NODES_MAX * NUM_FEAT];
__device__ __half g_kh[N_NODES_MAX * NUM_FEAT];

struct __align__(8) Half4 { __half2 a, b; };

// ---------------------------------------------------------------------------
// helpers
// ---------------------------------------------------------------------------
__device__ __forceinline__ uint32_t smem_u32(const void* p) {
    return static_cast<uint32_t>(__cvta_generic_to_shared(p));
}
__device__ __forceinline__ void ldsm_x4(uint32_t addr, uint32_t& r0, uint32_t& r1,
                                        uint32_t& r2, uint32_t& r3) {
    asm volatile("ldmatrix.sync.aligned.m8n8.x4.shared.b16 {%0,%1,%2,%3}, [%4];"
                 : "=r"(r0), "=r"(r1), "=r"(r2), "=r"(r3) : "r"(addr));
}
__device__ __forceinline__ void mma16816(float* c, const uint32_t* a,
                                         const uint32_t* b) {
    asm volatile(
        "mma.sync.aligned.m16n8k16.row.col.f32.f16.f16.f32 "
        "{%0,%1,%2,%3}, {%4,%5,%6,%7}, {%8,%9}, {%0,%1,%2,%3};"
        : "+f"(c[0]), "+f"(c[1]), "+f"(c[2]), "+f"(c[3])
        : "r"(a[0]), "r"(a[1]), "r"(a[2]), "r"(a[3]), "r"(b[0]), "r"(b[1]));
}

// ---------------------------------------------------------------------------
// Projection: fp16 tensor cores, fp32 inputs converted during the single
// full-K staging pass. C-tile 128x128; 8 warps as 4(m) x 2(n), warp tile
// 32x64. Smem pitch 136 halfs (272B) -> ldmatrix conflict-free.
// Also zero-inits `out` (y==0, z==0 blocks).
// ---------------------------------------------------------------------------
#define PITCH 136
#define PROJ_SMEM (2 * 128 * PITCH * 2)   // X + W tiles, bytes (69632)

__global__ __launch_bounds__(256, 2) void proj_kernel(
    const float* __restrict__ x,
    const float* __restrict__ Wq,
    const float* __restrict__ Wk,
    float* __restrict__ out, int out_n,
    int n_nodes)
{
    extern __shared__ __align__(16) __half psmem[];
    __half* Xh = psmem;                  // [128][PITCH]
    __half* Wh = psmem + 128 * PITCH;    // [128][PITCH]

    // Fold output zero-init into this kernel (out poisoned to 0xAA).
    if (blockIdx.y == 0 && blockIdx.z == 0) {
        for (int i = blockIdx.x * 256 + threadIdx.x; i < out_n;
             i += gridDim.x * 256)
            out[i] = 0.0f;
    }

    const int h    = blockIdx.y;
    const int row0 = blockIdx.x * 128;
    const bool is_k = (blockIdx.z != 0);
    const float* __restrict__ Wsrc = (is_k ? Wk : Wq) + h * F_HEAD * F_HEAD;
    __half* __restrict__ o_base = is_k ? g_kh : g_qh;
    const float scale = is_k ? 1.0f : INV_SQRT_FH;

    const int tid  = threadIdx.x;
    const int warp = tid >> 5;
    const int lane = tid & 31;
    const int wm   = (warp & 3) * 32;
    const int wn   = (warp >> 2) * 64;

    // ---- stage X and W (full K=128), fp32 -> fp16 conversion inline ----
    // 128 rows x 32 float4-chunks each; 256 threads -> 16 iters per array.
    #pragma unroll
    for (int t = tid; t < 128 * 32; t += 256) {
        const int r = t >> 5, c = t & 31;          // c: float4 chunk (4 floats)
        const int row = row0 + r;
        float4 xv = make_float4(0.f, 0.f, 0.f, 0.f);
        if (row < n_nodes)
            xv = *(const float4*)&x[(size_t)row * NUM_FEAT + h * F_HEAD + c * 4];
        __half2 hx[2];
        hx[0] = __floats2half2_rn(xv.x, xv.y);
        hx[1] = __floats2half2_rn(xv.z, xv.w);
        *(uint2*)&Xh[r * PITCH + c * 4] = *(const uint2*)hx;

        const float4 wv = *(const float4*)&Wsrc[(size_t)r * F_HEAD + c * 4];
        __half2 hw[2];
        hw[0] = __floats2half2_rn(wv.x, wv.y);
        hw[1] = __floats2half2_rn(wv.z, wv.w);
        *(uint2*)&Wh[r * PITCH + c * 4] = *(const uint2*)hw;
    }
    __syncthreads();

    // ---- fragment base addresses (validated R4/R6 pattern) ----
    uint32_t a_base[2];
    #pragma unroll
    for (int mi = 0; mi < 2; mi++)
        a_base[mi] = smem_u32(
            &Xh[(wm + mi * 16 + (lane & 15)) * PITCH + (lane >> 4) * 8]);

    uint32_t b_base[4];
    {
        const int nrow = (lane & 7) + ((lane >> 4) << 3);
        const int ksel = ((lane >> 3) & 1) * 8;
        #pragma unroll
        for (int nb = 0; nb < 4; nb++)
            b_base[nb] = smem_u32(&Wh[(wn + nb * 16 + nrow) * PITCH + ksel]);
    }

    float acc[2][8][4];
    #pragma unroll
    for (int mi = 0; mi < 2; mi++)
        #pragma unroll
        for (int ni = 0; ni < 8; ni++)
            #pragma unroll
            for (int c = 0; c < 4; c++) acc[mi][ni][c] = 0.0f;

    #pragma unroll
    for (int ki = 0; ki < 8; ki++) {
        const uint32_t koff = ki * 32;     // 16 halfs = 32B
        uint32_t af[2][4];
        #pragma unroll
        for (int mi = 0; mi < 2; mi++)
            ldsm_x4(a_base[mi] + koff, af[mi][0], af[mi][1], af[mi][2], af[mi][3]);

        uint32_t bf[8][2];
        #pragma unroll
        for (int nb = 0; nb < 4; nb++) {
            uint32_t r0, r1, r2, r3;
            ldsm_x4(b_base[nb] + koff, r0, r1, r2, r3);
            bf[nb * 2 + 0][0] = r0;  bf[nb * 2 + 0][1] = r1;
            bf[nb * 2 + 1][0] = r2;  bf[nb * 2 + 1][1] = r3;
        }

        #pragma unroll
        for (int mi = 0; mi < 2; mi++)
            #pragma unroll
            for (int ni = 0; ni < 8; ni++)
                mma16816(acc[mi][ni], af[mi], bf[ni]);
    }

    // ---- epilogue: scale + fp16 store ----
    #pragma unroll
    for (int mi = 0; mi < 2; mi++) {
        const int ra = row0 + wm + mi * 16 + (lane >> 2);
        const int rb = ra + 8;
        #pragma unroll
        for (int ni = 0; ni < 8; ni++) {
            const int col = h * F_HEAD + wn + ni * 8 + (lane & 3) * 2;
            if (ra < n_nodes)
                *(__half2*)(o_base + (size_t)ra * NUM_FEAT + col) =
                    __floats2half2_rn(acc[mi][ni][0] * scale, acc[mi][ni][1] * scale);
            if (rb < n_nodes)
                *(__half2*)(o_base + (size_t)rb * NUM_FEAT + col) =
                    __floats2half2_rn(acc[mi][ni][2] * scale, acc[mi][ni][3] * scale);
        }
    }
}

// ---------------------------------------------------------------------------
// Edge kernel: one warp per TWO edges (R4 version — best measured).
// ---------------------------------------------------------------------------
__global__ __launch_bounds__(256) void edge_kernel(
    const float* __restrict__ w_ij,
    const float* __restrict__ sph,
    const int*   __restrict__ idx_i,
    const int*   __restrict__ idx_j,
    const float* __restrict__ phi_r,
    const float* __restrict__ phi_chi,
    float* __restrict__ out,
    int n_pairs)
{
    const int gw   = (blockIdx.x * blockDim.x + threadIdx.x) >> 5;
    const int lane = threadIdx.x & 31;
    const int e0   = gw * 2;
    if (e0 >= n_pairs) return;
    const bool has2 = (e0 + 1 < n_pairs);
    const int e1 = has2 ? e0 + 1 : e0;

    const int ni0 = idx_i[e0], nj0 = idx_j[e0];
    const int ni1 = idx_i[e1], nj1 = idx_j[e1];

    const Half4*  __restrict__ q0 = (const Half4*)(g_qh + (size_t)ni0 * NUM_FEAT);
    const Half4*  __restrict__ k0 = (const Half4*)(g_kh + (size_t)nj0 * NUM_FEAT);
    const float4* __restrict__ w0 = (const float4*)(w_ij + (size_t)e0 * NUM_FEAT);
    const Half4*  __restrict__ q1 = (const Half4*)(g_qh + (size_t)ni1 * NUM_FEAT);
    const Half4*  __restrict__ k1 = (const Half4*)(g_kh + (size_t)nj1 * NUM_FEAT);
    const float4* __restrict__ w1 = (const float4*)(w_ij + (size_t)e1 * NUM_FEAT);

    float a0[NHEADS], a1[NHEADS];
    #pragma unroll
    for (int hh = 0; hh < NHEADS; hh++) {
        const int idx = lane + hh * 32;
        const float4 wv0 = __ldcs(&w0[idx]);
        const float4 wv1 = __ldcs(&w1[idx]);
        const Half4  qh0 = q0[idx];
        const Half4  kh0 = k0[idx];
        const Half4  qh1 = q1[idx];
        const Half4  kh1 = k1[idx];

        {
            const float2 qa = __half22float2(qh0.a), qb = __half22float2(qh0.b);
            const float2 ka = __half22float2(kh0.a), kb = __half22float2(kh0.b);
            a0[hh] = qa.x * wv0.x * ka.x + qa.y * wv0.y * ka.y
                   + qb.x * wv0.z * kb.x + qb.y * wv0.w * kb.y;
        }
        {
            const float2 qa = __half22float2(qh1.a), qb = __half22float2(qh1.b);
            const float2 ka = __half22float2(kh1.a), kb = __half22float2(kh1.b);
            a1[hh] = qa.x * wv1.x * ka.x + qa.y * wv1.y * ka.y
                   + qb.x * wv1.z * kb.x + qb.y * wv1.w * kb.y;
        }
    }

    #pragma unroll
    for (int off = 16; off > 0; off >>= 1) {
        #pragma unroll
        for (int hh = 0; hh < NHEADS; hh++) {
            a0[hh] += __shfl_xor_sync(0xFFFFFFFFu, a0[hh], off);
            a1[hh] += __shfl_xor_sync(0xFFFFFFFFu, a1[hh], off);
        }
    }

    const float cut0 = phi_r[e0] + phi_chi[e0];
    const float cut1 = phi_r[e1] + phi_chi[e1];

    if (lane < SPH_DIM) {
        const float al0 = (lane < 3 ? a0[0] : (lane < 8 ? a0[1] : a0[2])) * cut0;
        atomicAdd(&out[(size_t)ni0 * SPH_DIM + lane],
                  al0 * __ldcs(&sph[(size_t)e0 * SPH_DIM + lane]));
        if (has2) {
            const float al1 = (lane < 3 ? a1[0] : (lane < 8 ? a1[1] : a1[2])) * cut1;
            atomicAdd(&out[(size_t)ni1 * SPH_DIM + lane],
                      al1 * __ldcs(&sph[(size_t)e1 * SPH_DIM + lane]));
        }
    }
}

// ---------------------------------------------------------------------------
// Launch. Inputs (metadata order):
//  0: chi (unused)  1: sph_ij  2: x  3: w_ij  4: idx_i  5: phi_r_cut
//  6: phi_chi_cut   7: idx_j   8: Wq 9: Wk
// ---------------------------------------------------------------------------
extern "C" void kernel_launch(void* const* d_in, const int* in_sizes, int n_in,
                              void* d_out, int out_size)
{
    const float* sph     = (const float*)d_in[1];
    const float* x       = (const float*)d_in[2];
    const float* w_ij    = (const float*)d_in[3];
    const int*   idx_i   = (const int*)  d_in[4];
    const float* phi_r   = (const float*)d_in[5];
    const float* phi_chi = (const float*)d_in[6];
    const int*   idx_j   = (const int*)  d_in[7];
    const float* Wq      = (const float*)d_in[8];
    const float* Wk      = (const float*)d_in[9];
    float* out = (float*)d_out;

    const int n_nodes = in_sizes[2] / NUM_FEAT;
    const int n_pairs = in_sizes[4];

    cudaFuncSetAttribute(proj_kernel,
                         cudaFuncAttributeMaxDynamicSharedMemorySize,
                         PROJ_SMEM);

    // 1) projections (tensor cores, fp32 in, fp16 out; zero-init folded in)
    dim3 pgrid((n_nodes + 127) / 128, NHEADS, 2);
    proj_kernel<<<pgrid, 256, PROJ_SMEM>>>(x, Wq, Wk, out, out_size, n_nodes);

    // 2) edge attention + scatter
    const int edges_per_block = (256 / 32) * 2;
    const int eblocks = (n_pairs + edges_per_block - 1) / edges_per_block;
    edge_kernel<<<eblocks, 256>>>(w_ij, sph, idx_i, idx_j, phi_r, phi_chi,
                                  out, n_pairs);
}